// round 3
// baseline (speedup 1.0000x reference)
#include <cuda_runtime.h>
#include <math.h>

// RecurrentAttention: B=128, S=8192, D=64
//   scores[b,s] = sum_d x[b,s,d] * v[d]
//   alpha[b,s]  = softmax_s(scores[b,s])
//   out[b,d]    = sum_s alpha[b,s] * x[b,s,d]
// Output buffer layout (reference returns (out, alpha)):
//   d_out[0 .. B*D)            : out  (float32)
//   d_out[B*D .. B*D + B*S)    : alpha (float32)
//
// One CTA per batch row. Single pass over x with online softmax
// (flash-attention style); raw scores staged in SMEM (32 KB), alpha
// materialized in a cheap epilogue. HBM traffic ~273 MB total.

#define BB 128
#define SS 8192
#define DD 64
#define NWARPS 32
#define RPW (SS / NWARPS)   // 256 rows per warp
#define UU 8                // unroll factor -> 8 loads in flight per warp

__global__ __launch_bounds__(1024, 1)
void recurrent_attention_kernel(const float* __restrict__ x,
                                const float* __restrict__ v,
                                float* __restrict__ out,
                                float* __restrict__ alpha)
{
    __shared__ float s_scores[SS];          // 32 KB
    __shared__ float s_m[NWARPS];
    __shared__ float s_l[NWARPS];
    __shared__ float s_acc[NWARPS * DD];    // 8 KB
    __shared__ float s_factor[NWARPS];
    __shared__ float s_M, s_invL;

    const int b    = blockIdx.x;
    const int tid  = threadIdx.x;
    const int w    = tid >> 5;
    const int lane = tid & 31;

    // Each lane owns dims (2*lane, 2*lane+1)
    const float v0 = v[2 * lane];
    const float v1 = v[2 * lane + 1];

    // Warp w handles contiguous rows [w*RPW, (w+1)*RPW)
    const float2* xrow =
        reinterpret_cast<const float2*>(x + ((size_t)b * SS + (size_t)w * RPW) * DD) + lane;
    // row stride in float2 units = DD/2 = 32

    float m  = -3.0e38f;
    float l  = 0.0f;
    float a0 = 0.0f, a1 = 0.0f;

    const int score_base = w * RPW;

    for (int i = 0; i < RPW; i += UU) {
        float2 xv[UU];
        #pragma unroll
        for (int u = 0; u < UU; u++)
            xv[u] = xrow[(i + u) * (DD / 2)];

        #pragma unroll
        for (int u = 0; u < UU; u++) {
            // score = sum_d x[s,d]*v[d] : partial dot + butterfly reduce
            float p = fmaf(xv[u].x, v0, xv[u].y * v1);
            p += __shfl_xor_sync(0xffffffffu, p, 16);
            p += __shfl_xor_sync(0xffffffffu, p, 8);
            p += __shfl_xor_sync(0xffffffffu, p, 4);
            p += __shfl_xor_sync(0xffffffffu, p, 2);
            p += __shfl_xor_sync(0xffffffffu, p, 1);

            if (lane == 0) s_scores[score_base + i + u] = p;

            // Online softmax update (branch is warp-uniform: p,m identical on all lanes)
            if (p <= m) {
                float wt = __expf(p - m);
                l += wt;
                a0 = fmaf(wt, xv[u].x, a0);
                a1 = fmaf(wt, xv[u].y, a1);
            } else {
                float corr = __expf(m - p);
                l  = fmaf(l,  corr, 1.0f);
                a0 = fmaf(a0, corr, xv[u].x);
                a1 = fmaf(a1, corr, xv[u].y);
                m  = p;
            }
        }
    }

    if (lane == 0) { s_m[w] = m; s_l[w] = l; }
    s_acc[w * DD + 2 * lane]     = a0;
    s_acc[w * DD + 2 * lane + 1] = a1;
    __syncthreads();

    // Warp 0: merge the 32 per-warp (m,l) states
    if (w == 0) {
        float mw = s_m[lane];
        float M  = mw;
        #pragma unroll
        for (int o = 16; o; o >>= 1) M = fmaxf(M, __shfl_xor_sync(0xffffffffu, M, o));
        float f  = __expf(mw - M);
        float lw = s_l[lane] * f;
        #pragma unroll
        for (int o = 16; o; o >>= 1) lw += __shfl_xor_sync(0xffffffffu, lw, o);
        s_factor[lane] = f;
        if (lane == 0) { s_M = M; s_invL = 1.0f / lw; }
    }
    __syncthreads();

    const float M    = s_M;
    const float invL = s_invL;

    // out[b,d] = (sum_w acc_w[d] * exp(m_w - M)) / L
    if (tid < DD) {
        float acc = 0.0f;
        #pragma unroll
        for (int ww = 0; ww < NWARPS; ww++)
            acc = fmaf(s_acc[ww * DD + tid], s_factor[ww], acc);
        out[b * DD + tid] = acc * invL;
    }

    // alpha[b,s] = exp(score - M) / L  — vectorized float4 writes
    float4* aout = reinterpret_cast<float4*>(alpha + (size_t)b * SS);
    const float4* sin = reinterpret_cast<const float4*>(s_scores);
    for (int s4 = tid; s4 < SS / 4; s4 += 1024) {
        float4 sc = sin[s4];
        float4 r;
        r.x = __expf(sc.x - M) * invL;
        r.y = __expf(sc.y - M) * invL;
        r.z = __expf(sc.z - M) * invL;
        r.w = __expf(sc.w - M) * invL;
        aout[s4] = r;
    }
}

extern "C" void kernel_launch(void* const* d_in, const int* in_sizes, int n_in,
                              void* d_out, int out_size)
{
    const float* x = (const float*)d_in[0];   // (B, S, D) fp32
    const float* v = (const float*)d_in[1];   // (D, 1)    fp32
    float* out   = (float*)d_out;             // first B*D elements
    float* alpha = out + (size_t)BB * DD;     // next B*S elements

    recurrent_attention_kernel<<<BB, 1024>>>(x, v, out, alpha);
}

// round 4
// speedup vs baseline: 1.0031x; 1.0031x over previous
#include <cuda_runtime.h>
#include <math.h>

// RecurrentAttention: B=128, S=8192, D=64
//   scores[b,s] = sum_d x[b,s,d] * v[d]
//   alpha[b,s]  = softmax_s(scores[b,s])
//   out[b,d]    = sum_s alpha[b,s] * x[b,s,d]
// Output buffer layout (reference returns (out, alpha)):
//   d_out[0 .. B*D)            : out  (float32)
//   d_out[B*D .. B*D + B*S)    : alpha (float32)
//
// One CTA per batch row. Single pass over x with online softmax
// (flash-attention style); raw scores staged in SMEM (32 KB), alpha
// materialized in a cheap epilogue. HBM traffic ~273 MB total.

#define BB 128
#define SS 8192
#define DD 64
#define NWARPS 32
#define RPW (SS / NWARPS)   // 256 rows per warp
#define UU 8                // unroll factor -> 8 loads in flight per warp

__global__ __launch_bounds__(1024, 1)
void recurrent_attention_kernel(const float* __restrict__ x,
                                const float* __restrict__ v,
                                float* __restrict__ out,
                                float* __restrict__ alpha)
{
    __shared__ float s_scores[SS];          // 32 KB
    __shared__ float s_m[NWARPS];
    __shared__ float s_l[NWARPS];
    __shared__ float s_acc[NWARPS * DD];    // 8 KB
    __shared__ float s_factor[NWARPS];
    __shared__ float s_M, s_invL;

    const int b    = blockIdx.x;
    const int tid  = threadIdx.x;
    const int w    = tid >> 5;
    const int lane = tid & 31;

    // Each lane owns dims (2*lane, 2*lane+1)
    const float v0 = v[2 * lane];
    const float v1 = v[2 * lane + 1];

    // Warp w handles contiguous rows [w*RPW, (w+1)*RPW)
    const float2* xrow =
        reinterpret_cast<const float2*>(x + ((size_t)b * SS + (size_t)w * RPW) * DD) + lane;
    // row stride in float2 units = DD/2 = 32

    float m  = -3.0e38f;
    float l  = 0.0f;
    float a0 = 0.0f, a1 = 0.0f;

    const int score_base = w * RPW;

    for (int i = 0; i < RPW; i += UU) {
        float2 xv[UU];
        #pragma unroll
        for (int u = 0; u < UU; u++)
            xv[u] = xrow[(i + u) * (DD / 2)];

        #pragma unroll
        for (int u = 0; u < UU; u++) {
            // score = sum_d x[s,d]*v[d] : partial dot + butterfly reduce
            float p = fmaf(xv[u].x, v0, xv[u].y * v1);
            p += __shfl_xor_sync(0xffffffffu, p, 16);
            p += __shfl_xor_sync(0xffffffffu, p, 8);
            p += __shfl_xor_sync(0xffffffffu, p, 4);
            p += __shfl_xor_sync(0xffffffffu, p, 2);
            p += __shfl_xor_sync(0xffffffffu, p, 1);

            if (lane == 0) s_scores[score_base + i + u] = p;

            // Online softmax update (branch is warp-uniform: p,m identical on all lanes)
            if (p <= m) {
                float wt = __expf(p - m);
                l += wt;
                a0 = fmaf(wt, xv[u].x, a0);
                a1 = fmaf(wt, xv[u].y, a1);
            } else {
                float corr = __expf(m - p);
                l  = fmaf(l,  corr, 1.0f);
                a0 = fmaf(a0, corr, xv[u].x);
                a1 = fmaf(a1, corr, xv[u].y);
                m  = p;
            }
        }
    }

    if (lane == 0) { s_m[w] = m; s_l[w] = l; }
    s_acc[w * DD + 2 * lane]     = a0;
    s_acc[w * DD + 2 * lane + 1] = a1;
    __syncthreads();

    // Warp 0: merge the 32 per-warp (m,l) states
    if (w == 0) {
        float mw = s_m[lane];
        float M  = mw;
        #pragma unroll
        for (int o = 16; o; o >>= 1) M = fmaxf(M, __shfl_xor_sync(0xffffffffu, M, o));
        float f  = __expf(mw - M);
        float lw = s_l[lane] * f;
        #pragma unroll
        for (int o = 16; o; o >>= 1) lw += __shfl_xor_sync(0xffffffffu, lw, o);
        s_factor[lane] = f;
        if (lane == 0) { s_M = M; s_invL = 1.0f / lw; }
    }
    __syncthreads();

    const float M    = s_M;
    const float invL = s_invL;

    // out[b,d] = (sum_w acc_w[d] * exp(m_w - M)) / L
    if (tid < DD) {
        float acc = 0.0f;
        #pragma unroll
        for (int ww = 0; ww < NWARPS; ww++)
            acc = fmaf(s_acc[ww * DD + tid], s_factor[ww], acc);
        out[b * DD + tid] = acc * invL;
    }

    // alpha[b,s] = exp(score - M) / L  — vectorized float4 writes
    float4* aout = reinterpret_cast<float4*>(alpha + (size_t)b * SS);
    const float4* sin = reinterpret_cast<const float4*>(s_scores);
    for (int s4 = tid; s4 < SS / 4; s4 += 1024) {
        float4 sc = sin[s4];
        float4 r;
        r.x = __expf(sc.x - M) * invL;
        r.y = __expf(sc.y - M) * invL;
        r.z = __expf(sc.z - M) * invL;
        r.w = __expf(sc.w - M) * invL;
        aout[s4] = r;
    }
}

extern "C" void kernel_launch(void* const* d_in, const int* in_sizes, int n_in,
                              void* d_out, int out_size)
{
    const float* x = (const float*)d_in[0];   // (B, S, D) fp32
    const float* v = (const float*)d_in[1];   // (D, 1)    fp32
    float* out   = (float*)d_out;             // first B*D elements
    float* alpha = out + (size_t)BB * DD;     // next B*S elements

    recurrent_attention_kernel<<<BB, 1024>>>(x, v, out, alpha);
}